// round 9
// baseline (speedup 1.0000x reference)
#include <cuda_runtime.h>
#include <cstdint>

#define Cc 256
#define Hh 56
#define Ww 56
#define XPR 80
#define XPH 58

// ---- device scratch ----
__device__ float g_xt2[8 * 8 * 58 * 58 * 36];    // [b][cich][h58][w58][ci32+pad4], tf32
__device__ float g_wB[2 * 9 * 8 * 128 * 36];     // [mh][tap][cich][co128][k32+pad4], tf32
__device__ float g_xp[8 * 256 * XPH * XPR];      // SE path padded NCHW
__device__ float g_w1t[256 * 9 * 16];
__device__ float g_t[8 * 16 * 56 * 56];          // raw conv1 sums (atomic)
__device__ float g_a[8 * 56 * 56];

__device__ __forceinline__ uint32_t smem_u32(const void* p) {
    uint32_t a;
    asm("{ .reg .u64 t; cvta.to.shared.u64 t, %1; cvt.u32.u64 %0, t; }" : "=r"(a) : "l"(p));
    return a;
}
__device__ __forceinline__ float to_tf32(float v) {
    uint32_t u;
    asm("cvt.rn.tf32.f32 %0, %1;" : "=r"(u) : "f"(v));
    return __uint_as_float(u);
}
__device__ __forceinline__ void cp16g(void* s, const void* g) {
    unsigned sa = (unsigned)__cvta_generic_to_shared(s);
    asm volatile("cp.async.cg.shared.global [%0], [%1], 16;" ::"r"(sa), "l"(g));
}
#define CP_COMMIT() asm volatile("cp.async.commit_group;")
#define CP_WAIT0() asm volatile("cp.async.wait_group 0;")

__device__ __forceinline__ void mbar_init(uint32_t a, uint32_t c) {
    asm volatile("mbarrier.init.shared::cta.b64 [%0], %1;" ::"r"(a), "r"(c) : "memory");
}
__device__ __forceinline__ void mbar_expect(uint32_t a, uint32_t tx) {
    asm volatile("mbarrier.arrive.expect_tx.shared::cta.b64 _, [%0], %1;" ::"r"(a), "r"(tx)
                 : "memory");
}
__device__ __forceinline__ void mbar_wait(uint32_t a, int ph) {
    asm volatile(
        "{\n\t.reg .pred P;\nW%=:\n\t"
        "mbarrier.try_wait.parity.shared::cta.b64 P, [%0], %1;\n\t"
        "@!P bra W%=;\n\t}" ::"r"(a), "r"(ph) : "memory");
}
__device__ __forceinline__ void bulk_g2s(uint32_t dst, const void* src, uint32_t bytes,
                                         uint32_t mbar) {
    asm volatile(
        "cp.async.bulk.shared::cluster.global.mbarrier::complete_tx::bytes [%0], [%1], %2, [%3];"
        ::"r"(dst), "l"(src), "r"(bytes), "r"(mbar) : "memory");
}
__device__ __forceinline__ void mma8(float* d, const uint32_t* a, uint32_t b0,
                                     uint32_t b1) {
    asm volatile(
        "mma.sync.aligned.m16n8k8.row.col.f32.tf32.tf32.f32 "
        "{%0,%1,%2,%3}, {%4,%5,%6,%7}, {%8,%9}, {%0,%1,%2,%3};"
        : "+f"(d[0]), "+f"(d[1]), "+f"(d[2]), "+f"(d[3])
        : "r"(a[0]), "r"(a[1]), "r"(a[2]), "r"(a[3]), "r"(b0), "r"(b1));
}

// ---------------------------------------------------------------------------
// pad_x + zero_t fused (launch #1)
// ---------------------------------------------------------------------------
#define PADN (8 * 256 * XPH * XPH)
#define TN (8 * 16 * 56 * 56)
__global__ void prep_pad_zero(const float* __restrict__ x) {
    int idx = blockIdx.x * 256 + threadIdx.x;
    if (idx < PADN) {
        int w = idx % XPH, h = (idx / XPH) % XPH;
        int c = (idx / (XPH * XPH)) % 256, b = idx / (XPH * XPH * 256);
        float v = 0.f;
        if (h >= 1 && h < 57 && w >= 1 && w < 57)
            v = x[((b * 256 + c) * Hh + (h - 1)) * Ww + (w - 1)];
        g_xp[((b * 256 + c) * XPH + h) * XPR + w] = v;
    } else if (idx < PADN + TN) {
        g_t[idx - PADN] = 0.f;
    }
}

// NCHW -> [b][cich][h58][w58][36] padded tf32. block(32,8), grid(2, 448, 8)  (#2)
__global__ void transpose_x(const float* __restrict__ x) {
    __shared__ float t[32][33];
    int tx = threadIdx.x, ty = threadIdx.y;
    int wt = blockIdx.x, bh = blockIdx.y, cg = blockIdx.z;
    int b = bh / 56, h = bh % 56, w0 = wt * 32;
#pragma unroll
    for (int j = 0; j < 4; j++) {
        int ci = cg * 32 + ty + j * 8, w = w0 + tx;
        float v = 0.f;
        if (w < 56) v = x[((b * 256 + ci) * 56 + h) * 56 + w];
        t[ty + j * 8][tx] = to_tf32(v);
    }
    __syncthreads();
#pragma unroll
    for (int j = 0; j < 4; j++) {
        int w = w0 + ty + j * 8, ci = tx;
        if (w < 56)
            g_xt2[((size_t)((b * 8 + cg) * 58 + h + 1) * 58 + (w + 1)) * 36 + ci] =
                t[tx][ty + j * 8];
    }
}

// weights -> g_wB padded-36 single tf32; se_w1 transpose (#3)
__global__ void prep_w(const float* __restrict__ weight, const float* __restrict__ A_w,
                       const float* __restrict__ se_w1) {
    int idx = blockIdx.x * 256 + threadIdx.x;
    if (idx < 589824) {
        int k = idx & 31;
        int co = (idx >> 5) & 127;
        int rest = idx >> 12;
        int cich = rest & 7;
        rest >>= 3;
        int tap = rest % 9, mh = rest / 9;
        int ci = cich * 32 + k, cog = mh * 128 + co;
        float wp = weight[cog * 2304 + ci * 9 + tap] * A_w[ci * 9 + tap];
        g_wB[((size_t)((mh * 9 + tap) * 8 + cich) * 128 + co) * 36 + k] = to_tf32(wp);
    } else if (idx < 589824 + 36864) {
        int i2 = idx - 589824;
        int co = i2 & 15, tap = (i2 >> 4) % 9, ci = i2 / 144;
        g_w1t[i2] = se_w1[co * 2304 + ci * 9 + tap];
    }
}

// ---------------------------------------------------------------------------
// main_mma (launch #4 -> profiled): single-pass tf32 mma.sync shift-conv.
// grid(2 mh, 14 ht, 8 b), block 512 (16 warps = 4 m-warps x 4 n-warps).
// Warp tile 32co x 56n (one output row). Writes RAW conv to out (scaled later).
// ---------------------------------------------------------------------------
#define ABF 4608    // floats per A buffer (128 x 36)
#define BBF 12528   // floats per B buffer (6 x 58 x 36)
#define AB_BYTES 18432
#define BB_BYTES 50112
#define MAIN_SMEM ((2 * ABF + 2 * BBF) * 4)

__global__ __launch_bounds__(512, 1) void main_mma(float* __restrict__ out) {
    extern __shared__ __align__(16) float sm[];
    __shared__ __align__(8) unsigned long long mbs[4];  // A0,A1,B0,B1
    uint32_t smb = smem_u32(sm);
    uint32_t mba = smem_u32(mbs);
    int tid = threadIdx.x, lane = tid & 31, wid = tid >> 5;
    int mh = blockIdx.x, ht = blockIdx.y, b = blockIdx.z;
    int h0p = ht * 4;
    int mw = (wid >> 2) * 32;     // 0,32,64,96
    int row = wid & 3;            // each n-warp owns one output row
    int g = lane >> 2, t = lane & 3;

    if (tid == 0)
        for (int i = 0; i < 4; i++) mbar_init(mba + i * 8, 1);
    __syncthreads();

    float d[2][7][4];
#pragma unroll
    for (int mt = 0; mt < 2; mt++)
#pragma unroll
        for (int nt = 0; nt < 7; nt++)
#pragma unroll
            for (int r = 0; r < 4; r++) d[mt][nt][r] = 0.f;

    auto issueA = [&](int p) {
        int buf = p & 1;
        const float* src = g_wB + (size_t)((mh * 9 + (p % 9)) * 8 + (p / 9)) * 128 * 36;
        mbar_expect(mba + buf * 8, AB_BYTES);
        bulk_g2s(smb + buf * AB_BYTES, src, AB_BYTES, mba + buf * 8);
    };
    auto issueB = [&](int c) {
        int buf = c & 1;
        const float* src = g_xt2 + ((size_t)(b * 8 + c) * 58 + h0p) * 58 * 36;
        mbar_expect(mba + 16 + buf * 8, BB_BYTES);
        bulk_g2s(smb + 2 * AB_BYTES + buf * BBF * 4, src, BB_BYTES, mba + 16 + buf * 8);
    };

    if (tid == 0) {
        issueA(0);
        issueB(0);
    }

    int p = 0;
    for (int c = 0; c < 8; c++) {
        mbar_wait(mba + 16 + (c & 1) * 8, (c >> 1) & 1);
        const float* Bs = sm + 2 * ABF + (c & 1) * BBF;
#pragma unroll 1
        for (int tap = 0; tap < 9; tap++, p++) {
            mbar_wait(mba + (p & 1) * 8, (p >> 1) & 1);
            __syncthreads();
            if (tid == 0) {
                if (p + 1 < 72) issueA(p + 1);
                if (tap == 0 && c + 1 < 8) issueB(c + 1);
            }
            int dy = tap / 3, dx = tap % 3;
            const float* As = sm + (p & 1) * ABF;
            const float* pBr = Bs + ((row + dy) * 58 + g + dx) * 36 + t;
            const float* pA = As + (mw + g) * 36 + t;
#pragma unroll
            for (int k8 = 0; k8 < 4; k8++) {
                int k0 = k8 * 8;
                uint32_t a[2][4];
#pragma unroll
                for (int mt = 0; mt < 2; mt++) {
                    const float* ap = pA + mt * 16 * 36 + k0;
                    a[mt][0] = __float_as_uint(ap[0]);
                    a[mt][1] = __float_as_uint(ap[8 * 36]);
                    a[mt][2] = __float_as_uint(ap[4]);
                    a[mt][3] = __float_as_uint(ap[8 * 36 + 4]);
                }
#pragma unroll
                for (int nt = 0; nt < 7; nt++) {
                    const float* bp = pBr + nt * 8 * 36 + k0;
                    uint32_t b0 = __float_as_uint(bp[0]);
                    uint32_t b1 = __float_as_uint(bp[4]);
                    mma8(d[0][nt], a[0], b0, b1);
                    mma8(d[1][nt], a[1], b0, b1);
                }
            }
        }
    }

    // Epilogue: store RAW conv output (attention scaling in scale_out).
#pragma unroll
    for (int mt = 0; mt < 2; mt++) {
        int co = mh * 128 + mw + mt * 16 + g;
        float* ob = out + (size_t)(b * 256 + co) * 3136;
        float* ob2 = ob + 8 * 3136;
#pragma unroll
        for (int nt = 0; nt < 7; nt++) {
            int off = (h0p + row) * 56 + nt * 8 + t * 2;
            ob[off] = d[mt][nt][0];
            ob[off + 1] = d[mt][nt][1];
            ob2[off] = d[mt][nt][2];
            ob2[off + 1] = d[mt][nt][3];
        }
    }
}

// ---------------------------------------------------------------------------
// SE conv1 (#5): ci-split x4, atomic accumulate raw sums into g_t.
// ---------------------------------------------------------------------------
__global__ __launch_bounds__(256) void conv_se1() {
    __shared__ __align__(16) float xs[2][6][36];
    __shared__ __align__(16) float ws[2][9][16];
    int tid = threadIdx.x, cot = tid >> 5, lane = tid & 31;
    int row = lane >> 3, col0 = (lane & 7) << 2;
    int wt = blockIdx.x, ht = blockIdx.y, z = blockIdx.z;
    int b = z >> 2, cq = z & 3;
    int h0 = ht * 4, w0 = wt * 32;
    int ci0 = cq * 64;

    bool isx = tid < 54;
    int xr = tid / 9, xc = (tid % 9) * 4;
    bool isw = (tid >= 54) && (tid < 90);
    int wi = (tid - 54) * 4;
    const float* xpb = g_xp + (long long)b * 256 * XPH * XPR;

    unsigned long long acc[4];
#pragma unroll
    for (int p = 0; p < 4; p++) acc[p] = 0ULL;

    if (isx) cp16g(&xs[0][xr][xc], xpb + (size_t)ci0 * XPH * XPR + (h0 + xr) * XPR + (w0 + xc));
    if (isw) cp16g(&ws[0][0][wi], g_w1t + ci0 * 144 + wi);
    CP_COMMIT();

    int cur = 0;
    for (int i = 0; i < 64; i++) {
        CP_WAIT0();
        __syncthreads();
        if (i + 1 < 64) {
            int nb = cur ^ 1, ci = ci0 + i + 1;
            if (isx)
                cp16g(&xs[nb][xr][xc],
                      xpb + (size_t)ci * XPH * XPR + (h0 + xr) * XPR + (w0 + xc));
            if (isw) cp16g(&ws[nb][0][wi], g_w1t + ci * 144 + wi);
            CP_COMMIT();
        }
        const float(*X)[36] = xs[cur];
        const float(*W)[16] = ws[cur];
#pragma unroll
        for (int dy = 0; dy < 3; dy++) {
            unsigned long long xd[6];
#pragma unroll
            for (int p = 0; p < 6; p++) {
                unsigned int rr = __float_as_uint(X[row + dy][col0 + p]);
                asm("mov.b64 %0, {%1, %1};" : "=l"(xd[p]) : "r"(rr));
            }
#pragma unroll
            for (int dx = 0; dx < 3; dx++) {
                unsigned long long wv = *(const unsigned long long*)&W[dy * 3 + dx][cot << 1];
#pragma unroll
                for (int p = 0; p < 4; p++)
                    asm("fma.rn.f32x2 %0, %1, %2, %0;"
                        : "+l"(acc[p]) : "l"(wv), "l"(xd[p + dx]));
            }
        }
        cur ^= 1;
    }
    int h = h0 + row, co = cot << 1;
    float* t0 = g_t + ((b * 16 + co) * Hh + h) * Ww;
#pragma unroll
    for (int p = 0; p < 4; p++) {
        int w = w0 + col0 + p;
        if (w < Ww) {
            atomicAdd(t0 + w, __uint_as_float((unsigned)acc[p]));
            atomicAdd(t0 + Hh * Ww + w, __uint_as_float((unsigned)(acc[p] >> 32)));
        }
    }
}

// SE conv2 + sigmoid (#6), smem-staged t tile. grid(14 ht, 8 b), block 224.
__global__ __launch_bounds__(224) void conv_se2(const float* __restrict__ se_w2) {
    __shared__ float ws[144];
    __shared__ float ts[16][6][58];
    int tid = threadIdx.x;
    int ht = blockIdx.x, b = blockIdx.y;
    int h0 = ht * 4;
    if (tid < 144) ws[tid] = se_w2[tid];
    for (int i = tid; i < 16 * 6 * 58; i += 224) {
        int c = i % 58, r = (i / 58) % 6, ci = i / (58 * 6);
        int gh = h0 + r - 1, gw = c - 1;
        float v = 0.f;
        if (gh >= 0 && gh < Hh && gw >= 0 && gw < Ww)
            v = fmaxf(g_t[((b * 16 + ci) * Hh + gh) * Ww + gw], 0.f);
        ts[ci][r][c] = v;
    }
    __syncthreads();
    int rr = tid / 56, w = tid % 56;
    float sum = 0.f;
#pragma unroll 1
    for (int ci = 0; ci < 16; ci++)
#pragma unroll
        for (int dy = 0; dy < 3; dy++)
#pragma unroll
            for (int dx = 0; dx < 3; dx++)
                sum += ts[ci][rr + dy][w + dx] * ws[ci * 9 + dy * 3 + dx];
    g_a[(b * Hh + h0 + rr) * Ww + w] = 1.f / (1.f + __expf(-sum));
}

// scale_out (#7): out[b,c,h,w] *= a[b,h,w], vectorized x4.
__global__ __launch_bounds__(256) void scale_out(float* __restrict__ out) {
    int idx = blockIdx.x * 256 + threadIdx.x;  // idx over float4 elements
    if (idx >= 8 * 256 * 784) return;
    int hw4 = idx % 784;
    int c = (idx / 784) % 256;
    int b = idx / (784 * 256);
    float4 v = ((float4*)out)[idx];
    const float4 a = ((const float4*)g_a)[b * 784 + hw4];
    v.x *= a.x;
    v.y *= a.y;
    v.z *= a.z;
    v.w *= a.w;
    ((float4*)out)[idx] = v;
    (void)c;
}

// ---------------------------------------------------------------------------
extern "C" void kernel_launch(void* const* d_in, const int* in_sizes, int n_in,
                              void* d_out, int out_size) {
    const float* x = (const float*)d_in[0];
    const float* weight = (const float*)d_in[1];
    const float* A_w = (const float*)d_in[2];
    const float* se_w1 = (const float*)d_in[3];
    const float* se_w2 = (const float*)d_in[4];
    float* out = (float*)d_out;

    cudaFuncSetAttribute(main_mma, cudaFuncAttributeMaxDynamicSharedMemorySize, MAIN_SMEM);
    prep_pad_zero<<<(PADN + TN + 255) / 256, 256>>>(x);              // #1
    transpose_x<<<dim3(2, 8 * 56, 8), dim3(32, 8)>>>(x);             // #2
    prep_w<<<(589824 + 36864 + 255) / 256, 256>>>(weight, A_w, se_w1);  // #3
    main_mma<<<dim3(2, 14, 8), 512, MAIN_SMEM>>>(out);               // #4 (profiled)
    conv_se1<<<dim3(2, 14, 32), 256>>>();                            // #5
    conv_se2<<<dim3(14, 8), 224>>>(se_w2);                           // #6
    scale_out<<<(8 * 256 * 784 + 255) / 256, 256>>>(out);            // #7
}

// round 10
// speedup vs baseline: 1.1231x; 1.1231x over previous
#include <cuda_runtime.h>
#include <cstdint>

#define Cc 256
#define Hh 56
#define Ww 56
#define XPR 80
#define XPH 58

// ---- device scratch ----
__device__ float g_xt2[8 * 8 * 58 * 58 * 36];  // [b][cich][h58][w58][ci32+pad4], tf32
__device__ float g_wB[2 * 9 * 8 * 4096];       // [mh][tap][cich][frag4096], tf32 (reg-order)
__device__ float g_xp[8 * 256 * XPH * XPR];    // SE path padded NCHW
__device__ float g_w1t[256 * 9 * 16];
__device__ float g_t[8 * 16 * 56 * 56];        // raw conv1 sums (atomic)
__device__ float g_a[8 * 56 * 56];

__device__ __forceinline__ uint32_t smem_u32(const void* p) {
    uint32_t a;
    asm("{ .reg .u64 t; cvta.to.shared.u64 t, %1; cvt.u32.u64 %0, t; }" : "=r"(a) : "l"(p));
    return a;
}
__device__ __forceinline__ float to_tf32(float v) {
    uint32_t u;
    asm("cvt.rn.tf32.f32 %0, %1;" : "=r"(u) : "f"(v));
    return __uint_as_float(u);
}
__device__ __forceinline__ void cp16g(void* s, const void* g) {
    unsigned sa = (unsigned)__cvta_generic_to_shared(s);
    asm volatile("cp.async.cg.shared.global [%0], [%1], 16;" ::"r"(sa), "l"(g));
}
#define CP_COMMIT() asm volatile("cp.async.commit_group;")
#define CP_WAIT0() asm volatile("cp.async.wait_group 0;")

__device__ __forceinline__ void mbar_init(uint32_t a, uint32_t c) {
    asm volatile("mbarrier.init.shared::cta.b64 [%0], %1;" ::"r"(a), "r"(c) : "memory");
}
__device__ __forceinline__ void mbar_expect(uint32_t a, uint32_t tx) {
    asm volatile("mbarrier.arrive.expect_tx.shared::cta.b64 _, [%0], %1;" ::"r"(a), "r"(tx)
                 : "memory");
}
__device__ __forceinline__ void mbar_arrive(uint32_t a) {
    asm volatile("mbarrier.arrive.shared::cta.b64 _, [%0];" ::"r"(a) : "memory");
}
__device__ __forceinline__ void mbar_wait(uint32_t a, int ph) {
    asm volatile(
        "{\n\t.reg .pred P;\nW%=:\n\t"
        "mbarrier.try_wait.parity.shared::cta.b64 P, [%0], %1;\n\t"
        "@!P bra W%=;\n\t}" ::"r"(a), "r"(ph) : "memory");
}
__device__ __forceinline__ void bulk_g2s(uint32_t dst, const void* src, uint32_t bytes,
                                         uint32_t mbar) {
    asm volatile(
        "cp.async.bulk.shared::cluster.global.mbarrier::complete_tx::bytes [%0], [%1], %2, [%3];"
        ::"r"(dst), "l"(src), "r"(bytes), "r"(mbar) : "memory");
}
__device__ __forceinline__ void mma8(float* d, const uint32_t* a, uint32_t b0,
                                     uint32_t b1) {
    asm volatile(
        "mma.sync.aligned.m16n8k8.row.col.f32.tf32.tf32.f32 "
        "{%0,%1,%2,%3}, {%4,%5,%6,%7}, {%8,%9}, {%0,%1,%2,%3};"
        : "+f"(d[0]), "+f"(d[1]), "+f"(d[2]), "+f"(d[3])
        : "r"(a[0]), "r"(a[1]), "r"(a[2]), "r"(a[3]), "r"(b0), "r"(b1));
}

// ---------------------------------------------------------------------------
// pad_x + zero_t fused (#1)
// ---------------------------------------------------------------------------
#define PADN (8 * 256 * XPH * XPH)
#define TN (8 * 16 * 56 * 56)
__global__ void prep_pad_zero(const float* __restrict__ x) {
    int idx = blockIdx.x * 256 + threadIdx.x;
    if (idx < PADN) {
        int w = idx % XPH, h = (idx / XPH) % XPH;
        int c = (idx / (XPH * XPH)) % 256, b = idx / (XPH * XPH * 256);
        float v = 0.f;
        if (h >= 1 && h < 57 && w >= 1 && w < 57)
            v = x[((b * 256 + c) * Hh + (h - 1)) * Ww + (w - 1)];
        g_xp[((b * 256 + c) * XPH + h) * XPR + w] = v;
    } else if (idx < PADN + TN) {
        g_t[idx - PADN] = 0.f;
    }
}

// NCHW -> [b][cich][h58][w58][36] padded tf32. (#2)
__global__ void transpose_x(const float* __restrict__ x) {
    __shared__ float t[32][33];
    int tx = threadIdx.x, ty = threadIdx.y;
    int wt = blockIdx.x, bh = blockIdx.y, cg = blockIdx.z;
    int b = bh / 56, h = bh % 56, w0 = wt * 32;
#pragma unroll
    for (int j = 0; j < 4; j++) {
        int ci = cg * 32 + ty + j * 8, w = w0 + tx;
        float v = 0.f;
        if (w < 56) v = x[((b * 256 + ci) * 56 + h) * 56 + w];
        t[ty + j * 8][tx] = to_tf32(v);
    }
    __syncthreads();
#pragma unroll
    for (int j = 0; j < 4; j++) {
        int w = w0 + ty + j * 8, ci = tx;
        if (w < 56)
            g_xt2[((size_t)((b * 8 + cg) * 58 + h + 1) * 58 + (w + 1)) * 36 + ci] =
                t[tx][ty + j * 8];
    }
}

// weights -> g_wB in m16n8k8 register-fragment order; se_w1 transpose (#3)
// e layout: [mwi(4)][k8(4)][mt(2)][lane(32)][reg(4)] -> one LDS.128 per (mt,k8)
__global__ void prep_w(const float* __restrict__ weight, const float* __restrict__ A_w,
                       const float* __restrict__ se_w1) {
    int idx = blockIdx.x * 256 + threadIdx.x;
    if (idx < 589824) {
        int mh = idx / 294912;
        int rest = idx % 294912;
        int tap = rest / 32768;
        int r2 = rest % 32768;
        int cich = r2 >> 12;
        int e = r2 & 4095;
        int reg = e & 3, lane = (e >> 2) & 31, mt = (e >> 7) & 1;
        int k8 = (e >> 8) & 3, mwi = (e >> 10) & 3;
        int gg = lane >> 2, tt = lane & 3, half = reg >> 1, s = reg & 1;
        int row = mwi * 32 + mt * 16 + s * 8 + gg;
        int k = k8 * 8 + half * 4 + tt;
        int ci = cich * 32 + k, cog = mh * 128 + row;
        float wp = weight[cog * 2304 + ci * 9 + tap] * A_w[ci * 9 + tap];
        g_wB[((size_t)((mh * 9 + tap) * 8 + cich)) * 4096 + e] = to_tf32(wp);
    } else if (idx < 589824 + 36864) {
        int i2 = idx - 589824;
        int co = i2 & 15, tap = (i2 >> 4) % 9, ci = i2 / 144;
        g_w1t[i2] = se_w1[co * 2304 + ci * 9 + tap];
    }
}

// ---------------------------------------------------------------------------
// main_mma (#4, profiled): tf32 mma.sync shift-conv, barrier-free tap loop.
// grid(2 mh, 14 ht, 8 b), block 512. Warp tile 32co x 56n (one row).
// A: 4-stage pipeline (fullA/consA mbarriers); B: 2-stage halo reused 9 taps.
// ---------------------------------------------------------------------------
#define AB_BYTES 16384              // 4096 floats, frag-order
#define BBF 12528                   // floats per B buffer (6 x 58 x 36)
#define BB_BYTES 50112
#define A_REGION_F (4 * 4096)       // 16384 floats
#define MAIN_SMEM ((A_REGION_F + 2 * BBF) * 4)

__global__ __launch_bounds__(512, 1) void main_mma(float* __restrict__ out) {
    extern __shared__ __align__(16) float sm[];
    __shared__ __align__(8) unsigned long long mbs[12];
    uint32_t smb = smem_u32(sm);
    uint32_t mba = smem_u32(mbs);
    // layout: fullA[0..3]@0, consA[0..3]@32, fullB[0..1]@64, consB[0..1]@80
    int tid = threadIdx.x, lane = tid & 31, wid = tid >> 5;
    int mh = blockIdx.x, ht = blockIdx.y, b = blockIdx.z;
    int h0p = ht * 4;
    int mwi = wid >> 2;           // 0..3
    int row = wid & 3;            // output row within tile
    int g = lane >> 2, t = lane & 3;

    if (tid == 0) {
        for (int i = 0; i < 4; i++) mbar_init(mba + i * 8, 1);        // fullA
        for (int i = 0; i < 4; i++) mbar_init(mba + 32 + i * 8, 16);  // consA
        for (int i = 0; i < 2; i++) mbar_init(mba + 64 + i * 8, 1);   // fullB
        for (int i = 0; i < 2; i++) mbar_init(mba + 80 + i * 8, 16);  // consB
    }
    __syncthreads();

    float d[2][7][4];
#pragma unroll
    for (int mt = 0; mt < 2; mt++)
#pragma unroll
        for (int nt = 0; nt < 7; nt++)
#pragma unroll
            for (int r = 0; r < 4; r++) d[mt][nt][r] = 0.f;

    auto issueA = [&](int q) {
        const float* src = g_wB + (size_t)((mh * 9 + (q % 9)) * 8 + (q / 9)) * 4096;
        uint32_t mb = mba + (q & 3) * 8;
        mbar_expect(mb, AB_BYTES);
        bulk_g2s(smb + (q & 3) * AB_BYTES, src, AB_BYTES, mb);
    };
    auto issueB = [&](int c) {
        const float* src = g_xt2 + ((size_t)(b * 8 + c) * 58 + h0p) * 58 * 36;
        uint32_t mb = mba + 64 + (c & 1) * 8;
        mbar_expect(mb, BB_BYTES);
        bulk_g2s(smb + A_REGION_F * 4 + (c & 1) * BB_BYTES, src, BB_BYTES, mb);
    };

    if (tid == 0) {
        issueA(0);
        issueA(1);
        issueA(2);
        issueB(0);
    }

    int p = 0;
    for (int c = 0; c < 8; c++) {
        mbar_wait(mba + 64 + (c & 1) * 8, (c >> 1) & 1);  // fullB
        const float* Bs = sm + A_REGION_F + (c & 1) * BBF;
#pragma unroll 1
        for (int tap = 0; tap < 9; tap++, p++) {
            if (tid == 0) {  // producer: run 3 taps ahead
                int q = p + 3;
                if (q < 72) {
                    if (q >= 4) mbar_wait(mba + 32 + (q & 3) * 8, ((p - 1) >> 2) & 1);
                    issueA(q);
                }
                if (tap == 0 && c + 1 < 8) {
                    if (c + 1 >= 2)
                        mbar_wait(mba + 80 + ((c + 1) & 1) * 8, ((c - 1) >> 1) & 1);
                    issueB(c + 1);
                }
            }
            mbar_wait(mba + (p & 3) * 8, (p >> 2) & 1);  // fullA
            int dy = tap / 3, dx = tap % 3;
            const float4* As4 = (const float4*)(sm + (p & 3) * 4096);
            const float* pBr = Bs + ((row + dy) * 58 + g + dx) * 36 + t;
#pragma unroll
            for (int k8 = 0; k8 < 4; k8++) {
                int k0 = k8 * 8;
                float4 f0 = As4[((mwi * 4 + k8) * 2 + 0) * 32 + lane];
                float4 f1 = As4[((mwi * 4 + k8) * 2 + 1) * 32 + lane];
                uint32_t a0[4] = {__float_as_uint(f0.x), __float_as_uint(f0.y),
                                  __float_as_uint(f0.z), __float_as_uint(f0.w)};
                uint32_t a1[4] = {__float_as_uint(f1.x), __float_as_uint(f1.y),
                                  __float_as_uint(f1.z), __float_as_uint(f1.w)};
#pragma unroll
                for (int nt = 0; nt < 7; nt++) {
                    const float* bp = pBr + nt * 8 * 36 + k0;
                    uint32_t b0 = __float_as_uint(bp[0]);
                    uint32_t b1 = __float_as_uint(bp[4]);
                    mma8(d[0][nt], a0, b0, b1);
                    mma8(d[1][nt], a1, b0, b1);
                }
            }
            if (lane == 0) {
                mbar_arrive(mba + 32 + (p & 3) * 8);               // consA
                if (tap == 8) mbar_arrive(mba + 80 + (c & 1) * 8); // consB
            }
        }
    }

    // Epilogue: store RAW conv output (attention scaling in scale_out).
#pragma unroll
    for (int mt = 0; mt < 2; mt++) {
        int co = mh * 128 + mwi * 32 + mt * 16 + g;
        float* ob = out + (size_t)(b * 256 + co) * 3136;
        float* ob2 = ob + 8 * 3136;
#pragma unroll
        for (int nt = 0; nt < 7; nt++) {
            int off = (h0p + row) * 56 + nt * 8 + t * 2;
            ob[off] = d[mt][nt][0];
            ob[off + 1] = d[mt][nt][1];
            ob2[off] = d[mt][nt][2];
            ob2[off + 1] = d[mt][nt][3];
        }
    }
}

// ---------------------------------------------------------------------------
// SE conv1 (#5): ci-split x4, atomic accumulate raw sums into g_t. (proven)
// ---------------------------------------------------------------------------
__global__ __launch_bounds__(256) void conv_se1() {
    __shared__ __align__(16) float xs[2][6][36];
    __shared__ __align__(16) float ws[2][9][16];
    int tid = threadIdx.x, cot = tid >> 5, lane = tid & 31;
    int row = lane >> 3, col0 = (lane & 7) << 2;
    int wt = blockIdx.x, ht = blockIdx.y, z = blockIdx.z;
    int b = z >> 2, cq = z & 3;
    int h0 = ht * 4, w0 = wt * 32;
    int ci0 = cq * 64;

    bool isx = tid < 54;
    int xr = tid / 9, xc = (tid % 9) * 4;
    bool isw = (tid >= 54) && (tid < 90);
    int wi = (tid - 54) * 4;
    const float* xpb = g_xp + (long long)b * 256 * XPH * XPR;

    unsigned long long acc[4];
#pragma unroll
    for (int p = 0; p < 4; p++) acc[p] = 0ULL;

    if (isx) cp16g(&xs[0][xr][xc], xpb + (size_t)ci0 * XPH * XPR + (h0 + xr) * XPR + (w0 + xc));
    if (isw) cp16g(&ws[0][0][wi], g_w1t + ci0 * 144 + wi);
    CP_COMMIT();

    int cur = 0;
    for (int i = 0; i < 64; i++) {
        CP_WAIT0();
        __syncthreads();
        if (i + 1 < 64) {
            int nb = cur ^ 1, ci = ci0 + i + 1;
            if (isx)
                cp16g(&xs[nb][xr][xc],
                      xpb + (size_t)ci * XPH * XPR + (h0 + xr) * XPR + (w0 + xc));
            if (isw) cp16g(&ws[nb][0][wi], g_w1t + ci * 144 + wi);
            CP_COMMIT();
        }
        const float(*X)[36] = xs[cur];
        const float(*W)[16] = ws[cur];
#pragma unroll
        for (int dy = 0; dy < 3; dy++) {
            unsigned long long xd[6];
#pragma unroll
            for (int p = 0; p < 6; p++) {
                unsigned int rr = __float_as_uint(X[row + dy][col0 + p]);
                asm("mov.b64 %0, {%1, %1};" : "=l"(xd[p]) : "r"(rr));
            }
#pragma unroll
            for (int dx = 0; dx < 3; dx++) {
                unsigned long long wv = *(const unsigned long long*)&W[dy * 3 + dx][cot << 1];
#pragma unroll
                for (int p = 0; p < 4; p++)
                    asm("fma.rn.f32x2 %0, %1, %2, %0;"
                        : "+l"(acc[p]) : "l"(wv), "l"(xd[p + dx]));
            }
        }
        cur ^= 1;
    }
    int h = h0 + row, co = cot << 1;
    float* t0 = g_t + ((b * 16 + co) * Hh + h) * Ww;
#pragma unroll
    for (int p = 0; p < 4; p++) {
        int w = w0 + col0 + p;
        if (w < Ww) {
            atomicAdd(t0 + w, __uint_as_float((unsigned)acc[p]));
            atomicAdd(t0 + Hh * Ww + w, __uint_as_float((unsigned)(acc[p] >> 32)));
        }
    }
}

// SE conv2 + sigmoid (#6), smem-staged t tile. grid(14 ht, 8 b), block 224.
__global__ __launch_bounds__(224) void conv_se2(const float* __restrict__ se_w2) {
    __shared__ float ws[144];
    __shared__ float ts[16][6][58];
    int tid = threadIdx.x;
    int ht = blockIdx.x, b = blockIdx.y;
    int h0 = ht * 4;
    if (tid < 144) ws[tid] = se_w2[tid];
    for (int i = tid; i < 16 * 6 * 58; i += 224) {
        int c = i % 58, r = (i / 58) % 6, ci = i / (58 * 6);
        int gh = h0 + r - 1, gw = c - 1;
        float v = 0.f;
        if (gh >= 0 && gh < Hh && gw >= 0 && gw < Ww)
            v = fmaxf(g_t[((b * 16 + ci) * Hh + gh) * Ww + gw], 0.f);
        ts[ci][r][c] = v;
    }
    __syncthreads();
    int rr = tid / 56, w = tid % 56;
    float sum = 0.f;
#pragma unroll 1
    for (int ci = 0; ci < 16; ci++)
#pragma unroll
        for (int dy = 0; dy < 3; dy++)
#pragma unroll
            for (int dx = 0; dx < 3; dx++)
                sum += ts[ci][rr + dy][w + dx] * ws[ci * 9 + dy * 3 + dx];
    g_a[(b * Hh + h0 + rr) * Ww + w] = 1.f / (1.f + __expf(-sum));
}

// scale_out (#7): out[b,c,h,w] *= a[b,h,w], vectorized x4.
__global__ __launch_bounds__(256) void scale_out(float* __restrict__ out) {
    int idx = blockIdx.x * 256 + threadIdx.x;
    if (idx >= 8 * 256 * 784) return;
    int hw4 = idx % 784;
    int b = idx / (784 * 256);
    float4 v = ((float4*)out)[idx];
    const float4 a = ((const float4*)g_a)[b * 784 + hw4];
    v.x *= a.x;
    v.y *= a.y;
    v.z *= a.z;
    v.w *= a.w;
    ((float4*)out)[idx] = v;
}

// ---------------------------------------------------------------------------
extern "C" void kernel_launch(void* const* d_in, const int* in_sizes, int n_in,
                              void* d_out, int out_size) {
    const float* x = (const float*)d_in[0];
    const float* weight = (const float*)d_in[1];
    const float* A_w = (const float*)d_in[2];
    const float* se_w1 = (const float*)d_in[3];
    const float* se_w2 = (const float*)d_in[4];
    float* out = (float*)d_out;

    cudaFuncSetAttribute(main_mma, cudaFuncAttributeMaxDynamicSharedMemorySize, MAIN_SMEM);
    prep_pad_zero<<<(PADN + TN + 255) / 256, 256>>>(x);                 // #1
    transpose_x<<<dim3(2, 8 * 56, 8), dim3(32, 8)>>>(x);                // #2
    prep_w<<<(589824 + 36864 + 255) / 256, 256>>>(weight, A_w, se_w1);  // #3
    main_mma<<<dim3(2, 14, 8), 512, MAIN_SMEM>>>(out);                  // #4 (profiled)
    conv_se1<<<dim3(2, 14, 32), 256>>>();                               // #5
    conv_se2<<<dim3(14, 8), 224>>>(se_w2);                              // #6
    scale_out<<<(8 * 256 * 784 + 255) / 256, 256>>>(out);               // #7
}

// round 11
// speedup vs baseline: 1.2011x; 1.0695x over previous
#include <cuda_runtime.h>
#include <cstdint>

#define Cc 256
#define Hh 56
#define Ww 56
#define XPR 80
#define XPH 58

// ---- device scratch ----
__device__ float g_xt2[8 * 8 * 58 * 58 * 36];  // [b][cich][h58][w58][ci32+pad4], tf32
__device__ float g_wB[2 * 9 * 8 * 4096];       // [mh][tap][cich][frag4096], tf32 (reg-order)
__device__ float g_xp[8 * 256 * XPH * XPR];    // SE path padded NCHW (borders stay 0)
__device__ float g_w1t[256 * 9 * 16];
__device__ float g_t4[4 * 8 * 16 * 56 * 56];   // conv1 ci-partials (no atomics)
__device__ float g_a[8 * 56 * 56];

__device__ __forceinline__ uint32_t smem_u32(const void* p) {
    uint32_t a;
    asm("{ .reg .u64 t; cvta.to.shared.u64 t, %1; cvt.u32.u64 %0, t; }" : "=r"(a) : "l"(p));
    return a;
}
__device__ __forceinline__ float to_tf32(float v) {
    uint32_t u;
    asm("cvt.rn.tf32.f32 %0, %1;" : "=r"(u) : "f"(v));
    return __uint_as_float(u);
}
__device__ __forceinline__ void cp16g(void* s, const void* g) {
    unsigned sa = (unsigned)__cvta_generic_to_shared(s);
    asm volatile("cp.async.cg.shared.global [%0], [%1], 16;" ::"r"(sa), "l"(g));
}
#define CP_COMMIT() asm volatile("cp.async.commit_group;")
#define CP_WAIT0() asm volatile("cp.async.wait_group 0;")

__device__ __forceinline__ void mbar_init(uint32_t a, uint32_t c) {
    asm volatile("mbarrier.init.shared::cta.b64 [%0], %1;" ::"r"(a), "r"(c) : "memory");
}
__device__ __forceinline__ void mbar_expect(uint32_t a, uint32_t tx) {
    asm volatile("mbarrier.arrive.expect_tx.shared::cta.b64 _, [%0], %1;" ::"r"(a), "r"(tx)
                 : "memory");
}
__device__ __forceinline__ void mbar_arrive(uint32_t a) {
    asm volatile("mbarrier.arrive.shared::cta.b64 _, [%0];" ::"r"(a) : "memory");
}
__device__ __forceinline__ void mbar_wait(uint32_t a, int ph) {
    asm volatile(
        "{\n\t.reg .pred P;\nW%=:\n\t"
        "mbarrier.try_wait.parity.shared::cta.b64 P, [%0], %1;\n\t"
        "@!P bra W%=;\n\t}" ::"r"(a), "r"(ph) : "memory");
}
__device__ __forceinline__ void bulk_g2s(uint32_t dst, const void* src, uint32_t bytes,
                                         uint32_t mbar) {
    asm volatile(
        "cp.async.bulk.shared::cluster.global.mbarrier::complete_tx::bytes [%0], [%1], %2, [%3];"
        ::"r"(dst), "l"(src), "r"(bytes), "r"(mbar) : "memory");
}
__device__ __forceinline__ void mma8(float* d, const uint32_t* a, uint32_t b0,
                                     uint32_t b1) {
    asm volatile(
        "mma.sync.aligned.m16n8k8.row.col.f32.tf32.tf32.f32 "
        "{%0,%1,%2,%3}, {%4,%5,%6,%7}, {%8,%9}, {%0,%1,%2,%3};"
        : "+f"(d[0]), "+f"(d[1]), "+f"(d[2]), "+f"(d[3])
        : "r"(a[0]), "r"(a[1]), "r"(a[2]), "r"(a[3]), "r"(b0), "r"(b1));
}

// ---------------------------------------------------------------------------
// prep_all (#1): grid(2, 448, 11), block(32,8).
//  z<8 : transpose x -> g_xt2 (tf32) AND emit g_xp (exact, padded NCHW)
//  z>=8: weight->g_wB frag-order; se_w1 transpose (flat-index blocks)
// ---------------------------------------------------------------------------
__global__ void prep_all(const float* __restrict__ x, const float* __restrict__ weight,
                         const float* __restrict__ A_w, const float* __restrict__ se_w1) {
    int z = blockIdx.z;
    int tx = threadIdx.x, ty = threadIdx.y;
    if (z < 8) {
        __shared__ float t[32][33];
        int wt = blockIdx.x, bh = blockIdx.y, cg = z;
        int b = bh / 56, h = bh % 56, w0 = wt * 32;
#pragma unroll
        for (int j = 0; j < 4; j++) {
            int ci = cg * 32 + ty + j * 8, w = w0 + tx;
            float v = 0.f;
            if (w < 56) {
                v = x[((b * 256 + ci) * 56 + h) * 56 + w];
                g_xp[((size_t)(b * 256 + ci) * XPH + h + 1) * XPR + (w + 1)] = v;
            }
            t[ty + j * 8][tx] = to_tf32(v);
        }
        __syncthreads();
#pragma unroll
        for (int j = 0; j < 4; j++) {
            int w = w0 + ty + j * 8, ci = tx;
            if (w < 56)
                g_xt2[((size_t)((b * 8 + cg) * 58 + h + 1) * 58 + (w + 1)) * 36 + ci] =
                    t[tx][ty + j * 8];
        }
    } else {
        int tid = ty * 32 + tx;
        int bid = ((z - 8) * 448 + blockIdx.y) * 2 + blockIdx.x;
        int idx = bid * 256 + tid;
        if (idx < 589824) {
            int mh = idx / 294912;
            int rest = idx % 294912;
            int tap = rest / 32768;
            int r2 = rest % 32768;
            int cich = r2 >> 12;
            int e = r2 & 4095;
            int reg = e & 3, lane = (e >> 2) & 31, mt = (e >> 7) & 1;
            int k8 = (e >> 8) & 3, mwi = (e >> 10) & 3;
            int gg = lane >> 2, tt = lane & 3, half = reg >> 1, s = reg & 1;
            int row = mwi * 32 + mt * 16 + s * 8 + gg;
            int k = k8 * 8 + half * 4 + tt;
            int ci = cich * 32 + k, cog = mh * 128 + row;
            float wp = weight[cog * 2304 + ci * 9 + tap] * A_w[ci * 9 + tap];
            g_wB[((size_t)((mh * 9 + tap) * 8 + cich)) * 4096 + e] = to_tf32(wp);
        } else if (idx < 589824 + 36864) {
            int i2 = idx - 589824;
            int co = i2 & 15, tap = (i2 >> 4) % 9, ci = i2 / 144;
            g_w1t[i2] = se_w1[co * 2304 + ci * 9 + tap];
        }
    }
}

// ---------------------------------------------------------------------------
// SE conv1 (#2): ci-split x4 -> g_t4 partials (no atomics, no zeroing).
// ---------------------------------------------------------------------------
__global__ __launch_bounds__(256) void conv_se1() {
    __shared__ __align__(16) float xs[2][6][36];
    __shared__ __align__(16) float ws[2][9][16];
    int tid = threadIdx.x, cot = tid >> 5, lane = tid & 31;
    int row = lane >> 3, col0 = (lane & 7) << 2;
    int wt = blockIdx.x, ht = blockIdx.y, z = blockIdx.z;
    int b = z >> 2, cq = z & 3;
    int h0 = ht * 4, w0 = wt * 32;
    int ci0 = cq * 64;

    bool isx = tid < 54;
    int xr = tid / 9, xc = (tid % 9) * 4;
    bool isw = (tid >= 54) && (tid < 90);
    int wi = (tid - 54) * 4;
    const float* xpb = g_xp + (long long)b * 256 * XPH * XPR;

    unsigned long long acc[4];
#pragma unroll
    for (int p = 0; p < 4; p++) acc[p] = 0ULL;

    if (isx) cp16g(&xs[0][xr][xc], xpb + (size_t)ci0 * XPH * XPR + (h0 + xr) * XPR + (w0 + xc));
    if (isw) cp16g(&ws[0][0][wi], g_w1t + ci0 * 144 + wi);
    CP_COMMIT();

    int cur = 0;
    for (int i = 0; i < 64; i++) {
        CP_WAIT0();
        __syncthreads();
        if (i + 1 < 64) {
            int nb = cur ^ 1, ci = ci0 + i + 1;
            if (isx)
                cp16g(&xs[nb][xr][xc],
                      xpb + (size_t)ci * XPH * XPR + (h0 + xr) * XPR + (w0 + xc));
            if (isw) cp16g(&ws[nb][0][wi], g_w1t + ci * 144 + wi);
            CP_COMMIT();
        }
        const float(*X)[36] = xs[cur];
        const float(*W)[16] = ws[cur];
#pragma unroll
        for (int dy = 0; dy < 3; dy++) {
            unsigned long long xd[6];
#pragma unroll
            for (int p = 0; p < 6; p++) {
                unsigned int rr = __float_as_uint(X[row + dy][col0 + p]);
                asm("mov.b64 %0, {%1, %1};" : "=l"(xd[p]) : "r"(rr));
            }
#pragma unroll
            for (int dx = 0; dx < 3; dx++) {
                unsigned long long wv = *(const unsigned long long*)&W[dy * 3 + dx][cot << 1];
#pragma unroll
                for (int p = 0; p < 4; p++)
                    asm("fma.rn.f32x2 %0, %1, %2, %0;"
                        : "+l"(acc[p]) : "l"(wv), "l"(xd[p + dx]));
            }
        }
        cur ^= 1;
    }
    int h = h0 + row, co = cot << 1;
    float* t0 = g_t4 + (size_t)cq * 401408 + ((b * 16 + co) * Hh + h) * Ww;
#pragma unroll
    for (int p = 0; p < 4; p++) {
        int w = w0 + col0 + p;
        if (w < Ww) {
            t0[w] = __uint_as_float((unsigned)acc[p]);
            t0[Hh * Ww + w] = __uint_as_float((unsigned)(acc[p] >> 32));
        }
    }
}

// ---------------------------------------------------------------------------
// SE conv2 + sigmoid (#3): sum 4 partials, relu, conv, sigmoid -> g_a.
// ---------------------------------------------------------------------------
__global__ __launch_bounds__(224) void conv_se2(const float* __restrict__ se_w2) {
    __shared__ float ws[144];
    __shared__ float ts[16][6][58];
    int tid = threadIdx.x;
    int ht = blockIdx.x, b = blockIdx.y;
    int h0 = ht * 4;
    if (tid < 144) ws[tid] = se_w2[tid];
    for (int i = tid; i < 16 * 6 * 58; i += 224) {
        int c = i % 58, r = (i / 58) % 6, ci = i / (58 * 6);
        int gh = h0 + r - 1, gw = c - 1;
        float v = 0.f;
        if (gh >= 0 && gh < Hh && gw >= 0 && gw < Ww) {
            size_t off = (size_t)((b * 16 + ci) * Hh + gh) * Ww + gw;
            float s = g_t4[off] + g_t4[401408 + off] + g_t4[2 * 401408 + off] +
                      g_t4[3 * 401408 + off];
            v = fmaxf(s, 0.f);
        }
        ts[ci][r][c] = v;
    }
    __syncthreads();
    int rr = tid / 56, w = tid % 56;
    float sum = 0.f;
#pragma unroll 1
    for (int ci = 0; ci < 16; ci++)
#pragma unroll
        for (int dy = 0; dy < 3; dy++)
#pragma unroll
            for (int dx = 0; dx < 3; dx++)
                sum += ts[ci][rr + dy][w + dx] * ws[ci * 9 + dy * 3 + dx];
    g_a[(b * Hh + h0 + rr) * Ww + w] = 1.f / (1.f + __expf(-sum));
}

// ---------------------------------------------------------------------------
// main_mma (#4, profiled): tf32 mma.sync shift-conv, barrier-free tap loop,
// fused attention scaling in the epilogue.
// ---------------------------------------------------------------------------
#define AB_BYTES 16384
#define BBF 12528
#define BB_BYTES 50112
#define A_REGION_F (4 * 4096)
#define MAIN_SMEM ((A_REGION_F + 2 * BBF) * 4)

__global__ __launch_bounds__(512, 1) void main_mma(float* __restrict__ out) {
    extern __shared__ __align__(16) float sm[];
    __shared__ __align__(8) unsigned long long mbs[12];
    uint32_t smb = smem_u32(sm);
    uint32_t mba = smem_u32(mbs);
    int tid = threadIdx.x, lane = tid & 31, wid = tid >> 5;
    int mh = blockIdx.x, ht = blockIdx.y, b = blockIdx.z;
    int h0p = ht * 4;
    int mwi = wid >> 2;
    int row = wid & 3;
    int g = lane >> 2, t = lane & 3;

    if (tid == 0) {
        for (int i = 0; i < 4; i++) mbar_init(mba + i * 8, 1);        // fullA
        for (int i = 0; i < 4; i++) mbar_init(mba + 32 + i * 8, 16);  // consA
        for (int i = 0; i < 2; i++) mbar_init(mba + 64 + i * 8, 1);   // fullB
        for (int i = 0; i < 2; i++) mbar_init(mba + 80 + i * 8, 16);  // consB
    }
    __syncthreads();

    float d[2][7][4];
#pragma unroll
    for (int mt = 0; mt < 2; mt++)
#pragma unroll
        for (int nt = 0; nt < 7; nt++)
#pragma unroll
            for (int r = 0; r < 4; r++) d[mt][nt][r] = 0.f;

    auto issueA = [&](int q) {
        const float* src = g_wB + (size_t)((mh * 9 + (q % 9)) * 8 + (q / 9)) * 4096;
        uint32_t mb = mba + (q & 3) * 8;
        mbar_expect(mb, AB_BYTES);
        bulk_g2s(smb + (q & 3) * AB_BYTES, src, AB_BYTES, mb);
    };
    auto issueB = [&](int c) {
        const float* src = g_xt2 + ((size_t)(b * 8 + c) * 58 + h0p) * 58 * 36;
        uint32_t mb = mba + 64 + (c & 1) * 8;
        mbar_expect(mb, BB_BYTES);
        bulk_g2s(smb + A_REGION_F * 4 + (c & 1) * BB_BYTES, src, BB_BYTES, mb);
    };

    if (tid == 0) {
        issueA(0);
        issueA(1);
        issueA(2);
        issueB(0);
    }

    int p = 0;
    for (int c = 0; c < 8; c++) {
        mbar_wait(mba + 64 + (c & 1) * 8, (c >> 1) & 1);  // fullB
        const float* Bs = sm + A_REGION_F + (c & 1) * BBF;
#pragma unroll 1
        for (int tap = 0; tap < 9; tap++, p++) {
            if (tid == 0) {  // producer: 3 taps ahead
                int q = p + 3;
                if (q < 72) {
                    if (q >= 4) mbar_wait(mba + 32 + (q & 3) * 8, ((p - 1) >> 2) & 1);
                    issueA(q);
                }
                if (tap == 0 && c + 1 < 8) {
                    if (c + 1 >= 2)
                        mbar_wait(mba + 80 + ((c + 1) & 1) * 8, ((c - 1) >> 1) & 1);
                    issueB(c + 1);
                }
            }
            mbar_wait(mba + (p & 3) * 8, (p >> 2) & 1);  // fullA
            int dy = tap / 3, dx = tap % 3;
            const float4* As4 = (const float4*)(sm + (p & 3) * 4096);
            const float* pBr = Bs + ((row + dy) * 58 + g + dx) * 36 + t;
#pragma unroll
            for (int k8 = 0; k8 < 4; k8++) {
                int k0 = k8 * 8;
                float4 f0 = As4[((mwi * 4 + k8) * 2 + 0) * 32 + lane];
                float4 f1 = As4[((mwi * 4 + k8) * 2 + 1) * 32 + lane];
                uint32_t a0[4] = {__float_as_uint(f0.x), __float_as_uint(f0.y),
                                  __float_as_uint(f0.z), __float_as_uint(f0.w)};
                uint32_t a1[4] = {__float_as_uint(f1.x), __float_as_uint(f1.y),
                                  __float_as_uint(f1.z), __float_as_uint(f1.w)};
#pragma unroll
                for (int nt = 0; nt < 7; nt++) {
                    const float* bp = pBr + nt * 8 * 36 + k0;
                    uint32_t b0 = __float_as_uint(bp[0]);
                    uint32_t b1 = __float_as_uint(bp[4]);
                    mma8(d[0][nt], a0, b0, b1);
                    mma8(d[1][nt], a1, b0, b1);
                }
            }
            if (lane == 0) {
                mbar_arrive(mba + 32 + (p & 3) * 8);                // consA
                if (tap == 8) mbar_arrive(mba + 80 + (c & 1) * 8);  // consB
            }
        }
    }

    // Epilogue: fused attention scaling + store.
    const float* ga = g_a + (b * Hh + h0p + row) * Ww;
#pragma unroll
    for (int nt = 0; nt < 7; nt++) {
        int wc = nt * 8 + t * 2;
        float a0 = __ldg(ga + wc), a1 = __ldg(ga + wc + 1);
#pragma unroll
        for (int mt = 0; mt < 2; mt++) {
            int co = mh * 128 + mwi * 32 + mt * 16 + g;
            float* ob = out + (size_t)(b * 256 + co) * 3136 + (h0p + row) * 56 + wc;
            float* ob2 = ob + 8 * 3136;
            ob[0] = d[mt][nt][0] * a0;
            ob[1] = d[mt][nt][1] * a1;
            ob2[0] = d[mt][nt][2] * a0;
            ob2[1] = d[mt][nt][3] * a1;
        }
    }
}

// ---------------------------------------------------------------------------
extern "C" void kernel_launch(void* const* d_in, const int* in_sizes, int n_in,
                              void* d_out, int out_size) {
    const float* x = (const float*)d_in[0];
    const float* weight = (const float*)d_in[1];
    const float* A_w = (const float*)d_in[2];
    const float* se_w1 = (const float*)d_in[3];
    const float* se_w2 = (const float*)d_in[4];
    float* out = (float*)d_out;

    cudaFuncSetAttribute(main_mma, cudaFuncAttributeMaxDynamicSharedMemorySize, MAIN_SMEM);
    prep_all<<<dim3(2, 448, 11), dim3(32, 8)>>>(x, weight, A_w, se_w1);  // #1
    conv_se1<<<dim3(2, 14, 32), 256>>>();                                // #2
    conv_se2<<<dim3(14, 8), 224>>>(se_w2);                               // #3
    main_mma<<<dim3(2, 14, 8), 512, MAIN_SMEM>>>(out);                   // #4 (profiled)
}

// round 13
// speedup vs baseline: 1.3573x; 1.1301x over previous
#include <cuda_runtime.h>
#include <cstdint>

#define Cc 256
#define Hh 56
#define Ww 56
#define XPR 80
#define XPH 58

// ---- device scratch ----
__device__ float g_xt2[8 * 8 * 58 * 58 * 36];  // [b][cich][h58][w58][ci32+pad4], tf32
__device__ float g_wB[2 * 9 * 8 * 4096];       // [mh][tap][cich][frag4096], tf32 (reg-order)
__device__ float g_xp[8 * 256 * XPH * XPR];    // SE path padded NCHW (borders stay 0)
__device__ float g_w1t[256 * 9 * 16];
__device__ float g_t4[4 * 8 * 16 * 56 * 56];   // conv1 ci-partials (no atomics)
__device__ float g_a[8 * 56 * 56];

__device__ __forceinline__ uint32_t smem_u32(const void* p) {
    uint32_t a;
    asm("{ .reg .u64 t; cvta.to.shared.u64 t, %1; cvt.u32.u64 %0, t; }" : "=r"(a) : "l"(p));
    return a;
}
__device__ __forceinline__ float to_tf32(float v) {
    uint32_t u;
    asm("cvt.rn.tf32.f32 %0, %1;" : "=r"(u) : "f"(v));
    return __uint_as_float(u);
}
__device__ __forceinline__ void cp16g(void* s, const void* g) {
    unsigned sa = (unsigned)__cvta_generic_to_shared(s);
    asm volatile("cp.async.cg.shared.global [%0], [%1], 16;" ::"r"(sa), "l"(g));
}
#define CP_COMMIT() asm volatile("cp.async.commit_group;")
#define CP_WAIT0() asm volatile("cp.async.wait_group 0;")

__device__ __forceinline__ void mbar_init(uint32_t a, uint32_t c) {
    asm volatile("mbarrier.init.shared::cta.b64 [%0], %1;" ::"r"(a), "r"(c) : "memory");
}
__device__ __forceinline__ void mbar_expect(uint32_t a, uint32_t tx) {
    asm volatile("mbarrier.arrive.expect_tx.shared::cta.b64 _, [%0], %1;" ::"r"(a), "r"(tx)
                 : "memory");
}
__device__ __forceinline__ void mbar_arrive(uint32_t a) {
    asm volatile("mbarrier.arrive.shared::cta.b64 _, [%0];" ::"r"(a) : "memory");
}
__device__ __forceinline__ void mbar_wait(uint32_t a, int ph) {
    asm volatile(
        "{\n\t.reg .pred P;\nW%=:\n\t"
        "mbarrier.try_wait.parity.shared::cta.b64 P, [%0], %1;\n\t"
        "@!P bra W%=;\n\t}" ::"r"(a), "r"(ph) : "memory");
}
__device__ __forceinline__ void bulk_g2s(uint32_t dst, const void* src, uint32_t bytes,
                                         uint32_t mbar) {
    asm volatile(
        "cp.async.bulk.shared::cluster.global.mbarrier::complete_tx::bytes [%0], [%1], %2, [%3];"
        ::"r"(dst), "l"(src), "r"(bytes), "r"(mbar) : "memory");
}
__device__ __forceinline__ void mma8(float* d, const uint32_t* a, uint32_t b0,
                                     uint32_t b1) {
    asm volatile(
        "mma.sync.aligned.m16n8k8.row.col.f32.tf32.tf32.f32 "
        "{%0,%1,%2,%3}, {%4,%5,%6,%7}, {%8,%9}, {%0,%1,%2,%3};"
        : "+f"(d[0]), "+f"(d[1]), "+f"(d[2]), "+f"(d[3])
        : "r"(a[0]), "r"(a[1]), "r"(a[2]), "r"(a[3]), "r"(b0), "r"(b1));
}

// ---------------------------------------------------------------------------
// prep_all (#1): grid(2, 448, 11), block(32,8).
// ---------------------------------------------------------------------------
__global__ void prep_all(const float* __restrict__ x, const float* __restrict__ weight,
                         const float* __restrict__ A_w, const float* __restrict__ se_w1) {
    int z = blockIdx.z;
    int tx = threadIdx.x, ty = threadIdx.y;
    if (z < 8) {
        __shared__ float t[32][33];
        int wt = blockIdx.x, bh = blockIdx.y, cg = z;
        int b = bh / 56, h = bh % 56, w0 = wt * 32;
#pragma unroll
        for (int j = 0; j < 4; j++) {
            int ci = cg * 32 + ty + j * 8, w = w0 + tx;
            float v = 0.f;
            if (w < 56) {
                v = x[((b * 256 + ci) * 56 + h) * 56 + w];
                g_xp[((size_t)(b * 256 + ci) * XPH + h + 1) * XPR + (w + 1)] = v;
            }
            t[ty + j * 8][tx] = to_tf32(v);
        }
        __syncthreads();
#pragma unroll
        for (int j = 0; j < 4; j++) {
            int w = w0 + ty + j * 8, ci = tx;
            if (w < 56)
                g_xt2[((size_t)((b * 8 + cg) * 58 + h + 1) * 58 + (w + 1)) * 36 + ci] =
                    t[tx][ty + j * 8];
        }
    } else {
        int tid = ty * 32 + tx;
        int bid = ((z - 8) * 448 + blockIdx.y) * 2 + blockIdx.x;
        int idx = bid * 256 + tid;
        if (idx < 589824) {
            int mh = idx / 294912;
            int rest = idx % 294912;
            int tap = rest / 32768;
            int r2 = rest % 32768;
            int cich = r2 >> 12;
            int e = r2 & 4095;
            int reg = e & 3, lane = (e >> 2) & 31, mt = (e >> 7) & 1;
            int k8 = (e >> 8) & 3, mwi = (e >> 10) & 3;
            int gg = lane >> 2, tt = lane & 3, half = reg >> 1, s = reg & 1;
            int row = mwi * 32 + mt * 16 + s * 8 + gg;
            int k = k8 * 8 + half * 4 + tt;
            int ci = cich * 32 + k, cog = mh * 128 + row;
            float wp = weight[cog * 2304 + ci * 9 + tap] * A_w[ci * 9 + tap];
            g_wB[((size_t)((mh * 9 + tap) * 8 + cich)) * 4096 + e] = to_tf32(wp);
        } else if (idx < 589824 + 36864) {
            int i2 = idx - 589824;
            int co = i2 & 15, tap = (i2 >> 4) % 9, ci = i2 / 144;
            g_w1t[i2] = se_w1[co * 2304 + ci * 9 + tap];
        }
    }
}

// ---------------------------------------------------------------------------
// SE conv1 (#2): ci-split x4 -> g_t4 partials. (proven)
// ---------------------------------------------------------------------------
__global__ __launch_bounds__(256) void conv_se1() {
    __shared__ __align__(16) float xs[2][6][36];
    __shared__ __align__(16) float ws[2][9][16];
    int tid = threadIdx.x, cot = tid >> 5, lane = tid & 31;
    int row = lane >> 3, col0 = (lane & 7) << 2;
    int wt = blockIdx.x, ht = blockIdx.y, z = blockIdx.z;
    int b = z >> 2, cq = z & 3;
    int h0 = ht * 4, w0 = wt * 32;
    int ci0 = cq * 64;

    bool isx = tid < 54;
    int xr = tid / 9, xc = (tid % 9) * 4;
    bool isw = (tid >= 54) && (tid < 90);
    int wi = (tid - 54) * 4;
    const float* xpb = g_xp + (long long)b * 256 * XPH * XPR;

    unsigned long long acc[4];
#pragma unroll
    for (int p = 0; p < 4; p++) acc[p] = 0ULL;

    if (isx) cp16g(&xs[0][xr][xc], xpb + (size_t)ci0 * XPH * XPR + (h0 + xr) * XPR + (w0 + xc));
    if (isw) cp16g(&ws[0][0][wi], g_w1t + ci0 * 144 + wi);
    CP_COMMIT();

    int cur = 0;
    for (int i = 0; i < 64; i++) {
        CP_WAIT0();
        __syncthreads();
        if (i + 1 < 64) {
            int nb = cur ^ 1, ci = ci0 + i + 1;
            if (isx)
                cp16g(&xs[nb][xr][xc],
                      xpb + (size_t)ci * XPH * XPR + (h0 + xr) * XPR + (w0 + xc));
            if (isw) cp16g(&ws[nb][0][wi], g_w1t + ci * 144 + wi);
            CP_COMMIT();
        }
        const float(*X)[36] = xs[cur];
        const float(*W)[16] = ws[cur];
#pragma unroll
        for (int dy = 0; dy < 3; dy++) {
            unsigned long long xd[6];
#pragma unroll
            for (int p = 0; p < 6; p++) {
                unsigned int rr = __float_as_uint(X[row + dy][col0 + p]);
                asm("mov.b64 %0, {%1, %1};" : "=l"(xd[p]) : "r"(rr));
            }
#pragma unroll
            for (int dx = 0; dx < 3; dx++) {
                unsigned long long wv = *(const unsigned long long*)&W[dy * 3 + dx][cot << 1];
#pragma unroll
                for (int p = 0; p < 4; p++)
                    asm("fma.rn.f32x2 %0, %1, %2, %0;"
                        : "+l"(acc[p]) : "l"(wv), "l"(xd[p + dx]));
            }
        }
        cur ^= 1;
    }
    int h = h0 + row, co = cot << 1;
    float* t0 = g_t4 + (size_t)cq * 401408 + ((b * 16 + co) * Hh + h) * Ww;
#pragma unroll
    for (int p = 0; p < 4; p++) {
        int w = w0 + col0 + p;
        if (w < Ww) {
            t0[w] = __uint_as_float((unsigned)acc[p]);
            t0[Hh * Ww + w] = __uint_as_float((unsigned)(acc[p] >> 32));
        }
    }
}

// ---------------------------------------------------------------------------
// SE conv2 + sigmoid (#3): sum 4 partials, relu, conv, sigmoid -> g_a.
// ---------------------------------------------------------------------------
__global__ __launch_bounds__(224) void conv_se2(const float* __restrict__ se_w2) {
    __shared__ float ws[144];
    __shared__ float ts[16][6][58];
    int tid = threadIdx.x;
    int ht = blockIdx.x, b = blockIdx.y;
    int h0 = ht * 4;
    if (tid < 144) ws[tid] = se_w2[tid];
    for (int i = tid; i < 16 * 6 * 58; i += 224) {
        int c = i % 58, r = (i / 58) % 6, ci = i / (58 * 6);
        int gh = h0 + r - 1, gw = c - 1;
        float v = 0.f;
        if (gh >= 0 && gh < Hh && gw >= 0 && gw < Ww) {
            size_t off = (size_t)((b * 16 + ci) * Hh + gh) * Ww + gw;
            float s = g_t4[off] + g_t4[401408 + off] + g_t4[2 * 401408 + off] +
                      g_t4[3 * 401408 + off];
            v = fmaxf(s, 0.f);
        }
        ts[ci][r][c] = v;
    }
    __syncthreads();
    int rr = tid / 56, w = tid % 56;
    float sum = 0.f;
#pragma unroll 1
    for (int ci = 0; ci < 16; ci++)
#pragma unroll
        for (int dy = 0; dy < 3; dy++)
#pragma unroll
            for (int dx = 0; dx < 3; dx++)
                sum += ts[ci][rr + dy][w + dx] * ws[ci * 9 + dy * 3 + dx];
    g_a[(b * Hh + h0 + rr) * Ww + w] = 1.f / (1.f + __expf(-sum));
}

// ---------------------------------------------------------------------------
// main_mma (#4, profiled): tf32 mma.sync shift-conv, 2 CTAs/SM.
// grid(2 mh, 28 ht, 8 b) = 448 CTAs, block 256 (8 warps = 4 m x 2 rows).
// CTA tile 128co x 112n (2 rows x 56). A: 2-stage, B: 2-stage 4-row halo.
// Producer FIX vs R12: A(p+2) issued AFTER tap p fully consumed (wait consA).
// ---------------------------------------------------------------------------
#define AB_BYTES 16384
#define BBF 8352                 // 4 x 58 x 36 floats
#define BB_BYTES 33408
#define A_REGION_F (2 * 4096)
#define MAIN_SMEM ((A_REGION_F + 2 * BBF) * 4)

__global__ __launch_bounds__(256, 2) void main_mma(float* __restrict__ out) {
    extern __shared__ __align__(16) float sm[];
    __shared__ __align__(8) unsigned long long mbs[8];
    uint32_t smb = smem_u32(sm);
    uint32_t mba = smem_u32(mbs);
    // layout: fullA[0..1]@0, consA[0..1]@16, fullB[0..1]@32, consB[0..1]@48
    int tid = threadIdx.x, lane = tid & 31, wid = tid >> 5;
    int mh = blockIdx.x, ht = blockIdx.y, b = blockIdx.z;
    int h0p = ht * 2;
    int mwi = wid >> 1;  // 0..3
    int row = wid & 1;   // output row within tile
    int g = lane >> 2, t = lane & 3;

    if (tid == 0) {
        for (int i = 0; i < 2; i++) mbar_init(mba + i * 8, 1);       // fullA
        for (int i = 0; i < 2; i++) mbar_init(mba + 16 + i * 8, 8);  // consA
        for (int i = 0; i < 2; i++) mbar_init(mba + 32 + i * 8, 1);  // fullB
        for (int i = 0; i < 2; i++) mbar_init(mba + 48 + i * 8, 8);  // consB
    }
    __syncthreads();

    float d[2][7][4];
#pragma unroll
    for (int mt = 0; mt < 2; mt++)
#pragma unroll
        for (int nt = 0; nt < 7; nt++)
#pragma unroll
            for (int r = 0; r < 4; r++) d[mt][nt][r] = 0.f;

    auto issueA = [&](int q) {
        const float* src = g_wB + (size_t)((mh * 9 + (q % 9)) * 8 + (q / 9)) * 4096;
        uint32_t mb = mba + (q & 1) * 8;
        mbar_expect(mb, AB_BYTES);
        bulk_g2s(smb + (q & 1) * AB_BYTES, src, AB_BYTES, mb);
    };
    auto issueB = [&](int c) {
        const float* src = g_xt2 + ((size_t)(b * 8 + c) * 58 + h0p) * 58 * 36;
        uint32_t mb = mba + 32 + (c & 1) * 8;
        mbar_expect(mb, BB_BYTES);
        bulk_g2s(smb + A_REGION_F * 4 + (c & 1) * BB_BYTES, src, BB_BYTES, mb);
    };

    if (tid == 0) {
        issueA(0);
        issueA(1);
        issueB(0);
    }

    int p = 0;
    for (int c = 0; c < 8; c++) {
        mbar_wait(mba + 32 + (c & 1) * 8, (c >> 1) & 1);  // fullB
        const float* Bs = sm + A_REGION_F + (c & 1) * BBF;
#pragma unroll 1
        for (int tap = 0; tap < 9; tap++, p++) {
            if (tid == 0 && tap == 0 && c + 1 < 8) {  // B prefetch (correct in R12)
                if (c + 1 >= 2)
                    mbar_wait(mba + 48 + ((c + 1) & 1) * 8, ((c - 1) >> 1) & 1);
                issueB(c + 1);
            }
            mbar_wait(mba + (p & 1) * 8, (p >> 1) & 1);  // fullA
            int dy = tap / 3, dx = tap % 3;
            const float4* As4 = (const float4*)(sm + (p & 1) * 4096);
            const float* pBr = Bs + ((row + dy) * 58 + g + dx) * 36 + t;
#pragma unroll
            for (int k8 = 0; k8 < 4; k8++) {
                int k0 = k8 * 8;
                float4 f0 = As4[((mwi * 4 + k8) * 2 + 0) * 32 + lane];
                float4 f1 = As4[((mwi * 4 + k8) * 2 + 1) * 32 + lane];
                uint32_t a0[4] = {__float_as_uint(f0.x), __float_as_uint(f0.y),
                                  __float_as_uint(f0.z), __float_as_uint(f0.w)};
                uint32_t a1[4] = {__float_as_uint(f1.x), __float_as_uint(f1.y),
                                  __float_as_uint(f1.z), __float_as_uint(f1.w)};
#pragma unroll
                for (int nt = 0; nt < 7; nt++) {
                    const float* bp = pBr + nt * 8 * 36 + k0;
                    uint32_t b0 = __float_as_uint(bp[0]);
                    uint32_t b1 = __float_as_uint(bp[4]);
                    mma8(d[0][nt], a0, b0, b1);
                    mma8(d[1][nt], a1, b0, b1);
                }
            }
            if (lane == 0) {
                mbar_arrive(mba + 16 + (p & 1) * 8);                // consA
                if (tap == 8) mbar_arrive(mba + 48 + (c & 1) * 8);  // consB
            }
            // Producer: A(p+2) only after ALL warps consumed tap p (slot free).
            if (tid == 0 && p + 2 < 72) {
                mbar_wait(mba + 16 + (p & 1) * 8, (p >> 1) & 1);  // consA[p&1], k=p>>1
                issueA(p + 2);
            }
        }
    }

    // Epilogue: fused attention scaling + store.
    const float* ga = g_a + (b * Hh + h0p + row) * Ww;
#pragma unroll
    for (int nt = 0; nt < 7; nt++) {
        int wc = nt * 8 + t * 2;
        float a0 = __ldg(ga + wc), a1 = __ldg(ga + wc + 1);
#pragma unroll
        for (int mt = 0; mt < 2; mt++) {
            int co = mh * 128 + mwi * 32 + mt * 16 + g;
            float* ob = out + (size_t)(b * 256 + co) * 3136 + (h0p + row) * 56 + wc;
            float* ob2 = ob + 8 * 3136;
            ob[0] = d[mt][nt][0] * a0;
            ob[1] = d[mt][nt][1] * a1;
            ob2[0] = d[mt][nt][2] * a0;
            ob2[1] = d[mt][nt][3] * a1;
        }
    }
}

// ---------------------------------------------------------------------------
extern "C" void kernel_launch(void* const* d_in, const int* in_sizes, int n_in,
                              void* d_out, int out_size) {
    const float* x = (const float*)d_in[0];
    const float* weight = (const float*)d_in[1];
    const float* A_w = (const float*)d_in[2];
    const float* se_w1 = (const float*)d_in[3];
    const float* se_w2 = (const float*)d_in[4];
    float* out = (float*)d_out;

    cudaFuncSetAttribute(main_mma, cudaFuncAttributeMaxDynamicSharedMemorySize, MAIN_SMEM);
    prep_all<<<dim3(2, 448, 11), dim3(32, 8)>>>(x, weight, A_w, se_w1);  // #1
    conv_se1<<<dim3(2, 14, 32), 256>>>();                                // #2
    conv_se2<<<dim3(14, 8), 224>>>(se_w2);                               // #3
    main_mma<<<dim3(2, 28, 8), 256, MAIN_SMEM>>>(out);                   // #4 (profiled)
}

// round 15
// speedup vs baseline: 1.3669x; 1.0071x over previous
#include <cuda_runtime.h>
#include <cstdint>

#define Cc 256
#define Hh 56
#define Ww 56
#define XPR 80
#define XPH 58

// ---- device scratch ----
__device__ float g_xt2[8 * 8 * 58 * 58 * 36];  // [b][cich][h58][w58][ci32+pad4], tf32
__device__ float g_wB[2 * 9 * 8 * 4096];       // [mh][tap][cich][frag4096], tf32 (reg-order)
__device__ float g_xp[8 * 256 * XPH * XPR];    // SE path padded NCHW (borders stay 0)
__device__ float g_w1t[256 * 9 * 16];
__device__ float g_t4[4 * 8 * 16 * 56 * 56];   // conv1 ci-partials (no atomics)
__device__ float g_a[8 * 56 * 56];

__device__ __forceinline__ uint32_t smem_u32(const void* p) {
    uint32_t a;
    asm("{ .reg .u64 t; cvta.to.shared.u64 t, %1; cvt.u32.u64 %0, t; }" : "=r"(a) : "l"(p));
    return a;
}
__device__ __forceinline__ float to_tf32(float v) {
    uint32_t u;
    asm("cvt.rn.tf32.f32 %0, %1;" : "=r"(u) : "f"(v));
    return __uint_as_float(u);
}
__device__ __forceinline__ void cp16g(void* s, const void* g) {
    unsigned sa = (unsigned)__cvta_generic_to_shared(s);
    asm volatile("cp.async.cg.shared.global [%0], [%1], 16;" ::"r"(sa), "l"(g));
}
#define CP_COMMIT() asm volatile("cp.async.commit_group;")
#define CP_WAIT0() asm volatile("cp.async.wait_group 0;")

__device__ __forceinline__ void mbar_init(uint32_t a, uint32_t c) {
    asm volatile("mbarrier.init.shared::cta.b64 [%0], %1;" ::"r"(a), "r"(c) : "memory");
}
__device__ __forceinline__ void mbar_expect(uint32_t a, uint32_t tx) {
    asm volatile("mbarrier.arrive.expect_tx.shared::cta.b64 _, [%0], %1;" ::"r"(a), "r"(tx)
                 : "memory");
}
__device__ __forceinline__ void mbar_arrive(uint32_t a) {
    asm volatile("mbarrier.arrive.shared::cta.b64 _, [%0];" ::"r"(a) : "memory");
}
__device__ __forceinline__ void mbar_wait(uint32_t a, int ph) {
    asm volatile(
        "{\n\t.reg .pred P;\nW%=:\n\t"
        "mbarrier.try_wait.parity.shared::cta.b64 P, [%0], %1;\n\t"
        "@!P bra W%=;\n\t}" ::"r"(a), "r"(ph) : "memory");
}
__device__ __forceinline__ void bulk_g2s(uint32_t dst, const void* src, uint32_t bytes,
                                         uint32_t mbar) {
    asm volatile(
        "cp.async.bulk.shared::cluster.global.mbarrier::complete_tx::bytes [%0], [%1], %2, [%3];"
        ::"r"(dst), "l"(src), "r"(bytes), "r"(mbar) : "memory");
}
__device__ __forceinline__ void mma8(float* d, const uint32_t* a, uint32_t b0,
                                     uint32_t b1) {
    asm volatile(
        "mma.sync.aligned.m16n8k8.row.col.f32.tf32.tf32.f32 "
        "{%0,%1,%2,%3}, {%4,%5,%6,%7}, {%8,%9}, {%0,%1,%2,%3};"
        : "+f"(d[0]), "+f"(d[1]), "+f"(d[2]), "+f"(d[3])
        : "r"(a[0]), "r"(a[1]), "r"(a[2]), "r"(a[3]), "r"(b0), "r"(b1));
}

// ---------------------------------------------------------------------------
// prep_all: grid(2, 448, 11), block(32,8).
// ---------------------------------------------------------------------------
__global__ void prep_all(const float* __restrict__ x, const float* __restrict__ weight,
                         const float* __restrict__ A_w, const float* __restrict__ se_w1) {
    int z = blockIdx.z;
    int tx = threadIdx.x, ty = threadIdx.y;
    if (z < 8) {
        __shared__ float t[32][33];
        int wt = blockIdx.x, bh = blockIdx.y, cg = z;
        int b = bh / 56, h = bh % 56, w0 = wt * 32;
#pragma unroll
        for (int j = 0; j < 4; j++) {
            int ci = cg * 32 + ty + j * 8, w = w0 + tx;
            float v = 0.f;
            if (w < 56) {
                v = x[((b * 256 + ci) * 56 + h) * 56 + w];
                g_xp[((size_t)(b * 256 + ci) * XPH + h + 1) * XPR + (w + 1)] = v;
            }
            t[ty + j * 8][tx] = to_tf32(v);
        }
        __syncthreads();
#pragma unroll
        for (int j = 0; j < 4; j++) {
            int w = w0 + ty + j * 8, ci = tx;
            if (w < 56)
                g_xt2[((size_t)((b * 8 + cg) * 58 + h + 1) * 58 + (w + 1)) * 36 + ci] =
                    t[tx][ty + j * 8];
        }
    } else {
        int tid = ty * 32 + tx;
        int bid = ((z - 8) * 448 + blockIdx.y) * 2 + blockIdx.x;
        int idx = bid * 256 + tid;
        if (idx < 589824) {
            int mh = idx / 294912;
            int rest = idx % 294912;
            int tap = rest / 32768;
            int r2 = rest % 32768;
            int cich = r2 >> 12;
            int e = r2 & 4095;
            int reg = e & 3, lane = (e >> 2) & 31, mt = (e >> 7) & 1;
            int k8 = (e >> 8) & 3, mwi = (e >> 10) & 3;
            int gg = lane >> 2, tt = lane & 3, half = reg >> 1, s = reg & 1;
            int row = mwi * 32 + mt * 16 + s * 8 + gg;
            int k = k8 * 8 + half * 4 + tt;
            int ci = cich * 32 + k, cog = mh * 128 + row;
            float wp = weight[cog * 2304 + ci * 9 + tap] * A_w[ci * 9 + tap];
            g_wB[((size_t)((mh * 9 + tap) * 8 + cich)) * 4096 + e] = to_tf32(wp);
        } else if (idx < 589824 + 36864) {
            int i2 = idx - 589824;
            int co = i2 & 15, tap = (i2 >> 4) % 9, ci = i2 / 144;
            g_w1t[i2] = se_w1[co * 2304 + ci * 9 + tap];
        }
    }
}

// ---------------------------------------------------------------------------
// SE conv1: ci-split x4 -> g_t4 partials. (proven)
// ---------------------------------------------------------------------------
__global__ __launch_bounds__(256) void conv_se1() {
    __shared__ __align__(16) float xs[2][6][36];
    __shared__ __align__(16) float ws[2][9][16];
    int tid = threadIdx.x, cot = tid >> 5, lane = tid & 31;
    int row = lane >> 3, col0 = (lane & 7) << 2;
    int wt = blockIdx.x, ht = blockIdx.y, z = blockIdx.z;
    int b = z >> 2, cq = z & 3;
    int h0 = ht * 4, w0 = wt * 32;
    int ci0 = cq * 64;

    bool isx = tid < 54;
    int xr = tid / 9, xc = (tid % 9) * 4;
    bool isw = (tid >= 54) && (tid < 90);
    int wi = (tid - 54) * 4;
    const float* xpb = g_xp + (long long)b * 256 * XPH * XPR;

    unsigned long long acc[4];
#pragma unroll
    for (int p = 0; p < 4; p++) acc[p] = 0ULL;

    if (isx) cp16g(&xs[0][xr][xc], xpb + (size_t)ci0 * XPH * XPR + (h0 + xr) * XPR + (w0 + xc));
    if (isw) cp16g(&ws[0][0][wi], g_w1t + ci0 * 144 + wi);
    CP_COMMIT();

    int cur = 0;
    for (int i = 0; i < 64; i++) {
        CP_WAIT0();
        __syncthreads();
        if (i + 1 < 64) {
            int nb = cur ^ 1, ci = ci0 + i + 1;
            if (isx)
                cp16g(&xs[nb][xr][xc],
                      xpb + (size_t)ci * XPH * XPR + (h0 + xr) * XPR + (w0 + xc));
            if (isw) cp16g(&ws[nb][0][wi], g_w1t + ci * 144 + wi);
            CP_COMMIT();
        }
        const float(*X)[36] = xs[cur];
        const float(*W)[16] = ws[cur];
#pragma unroll
        for (int dy = 0; dy < 3; dy++) {
            unsigned long long xd[6];
#pragma unroll
            for (int p = 0; p < 6; p++) {
                unsigned int rr = __float_as_uint(X[row + dy][col0 + p]);
                asm("mov.b64 %0, {%1, %1};" : "=l"(xd[p]) : "r"(rr));
            }
#pragma unroll
            for (int dx = 0; dx < 3; dx++) {
                unsigned long long wv = *(const unsigned long long*)&W[dy * 3 + dx][cot << 1];
#pragma unroll
                for (int p = 0; p < 4; p++)
                    asm("fma.rn.f32x2 %0, %1, %2, %0;"
                        : "+l"(acc[p]) : "l"(wv), "l"(xd[p + dx]));
            }
        }
        cur ^= 1;
    }
    int h = h0 + row, co = cot << 1;
    float* t0 = g_t4 + (size_t)cq * 401408 + ((b * 16 + co) * Hh + h) * Ww;
#pragma unroll
    for (int p = 0; p < 4; p++) {
        int w = w0 + col0 + p;
        if (w < Ww) {
            t0[w] = __uint_as_float((unsigned)acc[p]);
            t0[Hh * Ww + w] = __uint_as_float((unsigned)(acc[p] >> 32));
        }
    }
}

// ---------------------------------------------------------------------------
// SE conv2 + sigmoid: sum 4 partials, relu, conv, sigmoid -> g_a.
// ---------------------------------------------------------------------------
__global__ __launch_bounds__(224) void conv_se2(const float* __restrict__ se_w2) {
    __shared__ float ws[144];
    __shared__ float ts[16][6][58];
    int tid = threadIdx.x;
    int ht = blockIdx.x, b = blockIdx.y;
    int h0 = ht * 4;
    if (tid < 144) ws[tid] = se_w2[tid];
    for (int i = tid; i < 16 * 6 * 58; i += 224) {
        int c = i % 58, r = (i / 58) % 6, ci = i / (58 * 6);
        int gh = h0 + r - 1, gw = c - 1;
        float v = 0.f;
        if (gh >= 0 && gh < Hh && gw >= 0 && gw < Ww) {
            size_t off = (size_t)((b * 16 + ci) * Hh + gh) * Ww + gw;
            float s = g_t4[off] + g_t4[401408 + off] + g_t4[2 * 401408 + off] +
                      g_t4[3 * 401408 + off];
            v = fmaxf(s, 0.f);
        }
        ts[ci][r][c] = v;
    }
    __syncthreads();
    int rr = tid / 56, w = tid % 56;
    float sum = 0.f;
#pragma unroll 1
    for (int ci = 0; ci < 16; ci++)
#pragma unroll
        for (int dy = 0; dy < 3; dy++)
#pragma unroll
            for (int dx = 0; dx < 3; dx++)
                sum += ts[ci][rr + dy][w + dx] * ws[ci * 9 + dy * 3 + dx];
    g_a[(b * Hh + h0 + rr) * Ww + w] = 1.f / (1.f + __expf(-sum));
}

// ---------------------------------------------------------------------------
// main_mma: tf32 mma.sync shift-conv, 2 CTAs/SM (proven R13), RAW output.
// ---------------------------------------------------------------------------
#define AB_BYTES 16384
#define BBF 8352
#define BB_BYTES 33408
#define A_REGION_F (2 * 4096)
#define MAIN_SMEM ((A_REGION_F + 2 * BBF) * 4)

__global__ __launch_bounds__(256, 2) void main_mma(float* __restrict__ out) {
    extern __shared__ __align__(16) float sm[];
    __shared__ __align__(8) unsigned long long mbs[8];
    uint32_t smb = smem_u32(sm);
    uint32_t mba = smem_u32(mbs);
    int tid = threadIdx.x, lane = tid & 31, wid = tid >> 5;
    int mh = blockIdx.x, ht = blockIdx.y, b = blockIdx.z;
    int h0p = ht * 2;
    int mwi = wid >> 1;
    int row = wid & 1;
    int g = lane >> 2, t = lane & 3;

    if (tid == 0) {
        for (int i = 0; i < 2; i++) mbar_init(mba + i * 8, 1);       // fullA
        for (int i = 0; i < 2; i++) mbar_init(mba + 16 + i * 8, 8);  // consA
        for (int i = 0; i < 2; i++) mbar_init(mba + 32 + i * 8, 1);  // fullB
        for (int i = 0; i < 2; i++) mbar_init(mba + 48 + i * 8, 8);  // consB
    }
    __syncthreads();

    float d[2][7][4];
#pragma unroll
    for (int mt = 0; mt < 2; mt++)
#pragma unroll
        for (int nt = 0; nt < 7; nt++)
#pragma unroll
            for (int r = 0; r < 4; r++) d[mt][nt][r] = 0.f;

    auto issueA = [&](int q) {
        const float* src = g_wB + (size_t)((mh * 9 + (q % 9)) * 8 + (q / 9)) * 4096;
        uint32_t mb = mba + (q & 1) * 8;
        mbar_expect(mb, AB_BYTES);
        bulk_g2s(smb + (q & 1) * AB_BYTES, src, AB_BYTES, mb);
    };
    auto issueB = [&](int c) {
        const float* src = g_xt2 + ((size_t)(b * 8 + c) * 58 + h0p) * 58 * 36;
        uint32_t mb = mba + 32 + (c & 1) * 8;
        mbar_expect(mb, BB_BYTES);
        bulk_g2s(smb + A_REGION_F * 4 + (c & 1) * BB_BYTES, src, BB_BYTES, mb);
    };

    if (tid == 0) {
        issueA(0);
        issueA(1);
        issueB(0);
    }

    int p = 0;
    for (int c = 0; c < 8; c++) {
        mbar_wait(mba + 32 + (c & 1) * 8, (c >> 1) & 1);  // fullB
        const float* Bs = sm + A_REGION_F + (c & 1) * BBF;
#pragma unroll 1
        for (int tap = 0; tap < 9; tap++, p++) {
            if (tid == 0 && tap == 0 && c + 1 < 8) {
                if (c + 1 >= 2)
                    mbar_wait(mba + 48 + ((c + 1) & 1) * 8, ((c - 1) >> 1) & 1);
                issueB(c + 1);
            }
            mbar_wait(mba + (p & 1) * 8, (p >> 1) & 1);  // fullA
            int dy = tap / 3, dx = tap % 3;
            const float4* As4 = (const float4*)(sm + (p & 1) * 4096);
            const float* pBr = Bs + ((row + dy) * 58 + g + dx) * 36 + t;
#pragma unroll
            for (int k8 = 0; k8 < 4; k8++) {
                int k0 = k8 * 8;
                float4 f0 = As4[((mwi * 4 + k8) * 2 + 0) * 32 + lane];
                float4 f1 = As4[((mwi * 4 + k8) * 2 + 1) * 32 + lane];
                uint32_t a0[4] = {__float_as_uint(f0.x), __float_as_uint(f0.y),
                                  __float_as_uint(f0.z), __float_as_uint(f0.w)};
                uint32_t a1[4] = {__float_as_uint(f1.x), __float_as_uint(f1.y),
                                  __float_as_uint(f1.z), __float_as_uint(f1.w)};
#pragma unroll
                for (int nt = 0; nt < 7; nt++) {
                    const float* bp = pBr + nt * 8 * 36 + k0;
                    uint32_t b0 = __float_as_uint(bp[0]);
                    uint32_t b1 = __float_as_uint(bp[4]);
                    mma8(d[0][nt], a0, b0, b1);
                    mma8(d[1][nt], a1, b0, b1);
                }
            }
            if (lane == 0) {
                mbar_arrive(mba + 16 + (p & 1) * 8);                // consA
                if (tap == 8) mbar_arrive(mba + 48 + (c & 1) * 8);  // consB
            }
            if (tid == 0 && p + 2 < 72) {
                mbar_wait(mba + 16 + (p & 1) * 8, (p >> 1) & 1);
                issueA(p + 2);
            }
        }
    }

    // Epilogue: RAW store (scaling in scale_out after SE join).
#pragma unroll
    for (int mt = 0; mt < 2; mt++) {
        int co = mh * 128 + mwi * 32 + mt * 16 + g;
        float* ob = out + (size_t)(b * 256 + co) * 3136;
        float* ob2 = ob + 8 * 3136;
#pragma unroll
        for (int nt = 0; nt < 7; nt++) {
            int off = (h0p + row) * 56 + nt * 8 + t * 2;
            ob[off] = d[mt][nt][0];
            ob[off + 1] = d[mt][nt][1];
            ob2[off] = d[mt][nt][2];
            ob2[off + 1] = d[mt][nt][3];
        }
    }
}

// scale_out: out[b,c,h,w] *= a[b,h,w]; idx indexes float4 elements.
// Total float4 elements = 8*256*3136/4 = 8*256*784.
__global__ __launch_bounds__(256) void scale_out(float* __restrict__ out) {
    int idx = blockIdx.x * 256 + threadIdx.x;
    if (idx >= 8 * 256 * 784) return;
    int hw4 = idx % 784;
    int b = idx / (784 * 256);
    float4 v = ((float4*)out)[idx];
    const float4 a = ((const float4*)g_a)[b * 784 + hw4];
    v.x *= a.x;
    v.y *= a.y;
    v.z *= a.z;
    v.w *= a.w;
    ((float4*)out)[idx] = v;
}

// ---------------------------------------------------------------------------
extern "C" void kernel_launch(void* const* d_in, const int* in_sizes, int n_in,
                              void* d_out, int out_size) {
    const float* x = (const float*)d_in[0];
    const float* weight = (const float*)d_in[1];
    const float* A_w = (const float*)d_in[2];
    const float* se_w1 = (const float*)d_in[3];
    const float* se_w2 = (const float*)d_in[4];
    float* out = (float*)d_out;

    static cudaStream_t s2 = nullptr;
    static cudaEvent_t evFork = nullptr, evJoin = nullptr;
    if (!s2) {
        cudaStreamCreateWithFlags(&s2, cudaStreamNonBlocking);
        cudaEventCreateWithFlags(&evFork, cudaEventDisableTiming);
        cudaEventCreateWithFlags(&evJoin, cudaEventDisableTiming);
        cudaFuncSetAttribute(main_mma, cudaFuncAttributeMaxDynamicSharedMemorySize,
                             MAIN_SMEM);
    }

    prep_all<<<dim3(2, 448, 11), dim3(32, 8)>>>(x, weight, A_w, se_w1);
    cudaEventRecord(evFork, 0);
    cudaStreamWaitEvent(s2, evFork, 0);
    // SE branch (stream s2) runs concurrently with main_mma (default stream).
    conv_se1<<<dim3(2, 14, 32), 256, 0, s2>>>();
    conv_se2<<<dim3(14, 8), 224, 0, s2>>>(se_w2);
    cudaEventRecord(evJoin, s2);
    main_mma<<<dim3(2, 28, 8), 256, MAIN_SMEM>>>(out);
    cudaStreamWaitEvent(0, evJoin, 0);
    // FIX vs R14: grid covers ALL 8*256*784 float4 elements (was /4 too small).
    scale_out<<<(8 * 256 * 784 + 255) / 256, 256>>>(out);
}